// round 9
// baseline (speedup 1.0000x reference)
#include <cuda_runtime.h>
#include <math.h>
#include <stdint.h>

#define B_    64
#define T_    1000
#define D_    512
#define V_    29
#define L_    200
#define S_    401            // 2*L + 1
#define CBLANK 28
#define NEGV  (-1e9f)
#define LOG2E 1.44269504088896340736f
#define LN2   0.69314718055994530942f

typedef unsigned long long u64;

// ---------------- device scratch (no allocations allowed) ----------------
__device__ float d_lp[(long)B_ * T_ * V_];   // LOG2-probs lp2[b][t][v], 7.4 MB
__device__ float d_loss[B_];

__device__ __forceinline__ float ex2f(float x){ float r; asm("ex2.approx.f32 %0, %1;" : "=f"(r) : "f"(x)); return r; }
__device__ __forceinline__ float lg2f(float x){ float r; asm("lg2.approx.f32 %0, %1;" : "=f"(r) : "f"(x)); return r; }

// exact 3-way log2-sum-exp via selects (no cancellation; NEGV-safe)
__device__ __forceinline__ float lse3(float a0, float a1, float a2)
{
    const float mab = fmaxf(a0, a1);
    const float nab = fminf(a0, a1);
    const float mx  = fmaxf(mab, a2);
    const float mn  = fminf(nab, a2);
    const float md  = fmaxf(nab, fminf(mab, a2));
    return mx + lg2f(1.0f + ex2f(mn - mx) + ex2f(md - mx));
}
// 2-way log2-sum-exp (blank states never take the skip transition)
__device__ __forceinline__ float lse2(float a0, float a1)
{
    const float mx = fmaxf(a0, a1);
    const float mn = fminf(a0, a1);
    return mx + lg2f(1.0f + ex2f(mn - mx));
}

#define FMA2(d, a, b) asm("fma.rn.f32x2 %0, %1, %2, %0;" : "+l"(d) : "l"(a), "l"(b))

// =====================================================================
// Kernel 1: logits = F @ W + b, log2_softmax, write d_lp.
// R7 structure, but 512 threads / thread tile 8 rows x 2 cols to double
// occupancy (regs ~95 -> 16 warps/SM). BM=256 rows/block (grid=250).
// F: cp.async double-buffered, row-major, XOR-swizzled smem.
// W: whole 512x32 transposed wT[col][k] (stride 516), resident in smem.
// FFMA2 pairs over k (lo=even-k, hi=odd-k partial sums).
// =====================================================================
#define BM2 256
#define WT_STRIDE 516
#define SMEM_GEMM_BYTES 132608

extern __shared__ char smem_dyn[];

__global__ __launch_bounds__(512, 1) void gemm_lsm_kernel(
    const float* __restrict__ F, const float* __restrict__ W,
    const float* __restrict__ bias)
{
    float* fbuf = (float*)smem_dyn;
    float* wT   = (float*)(smem_dyn + 65536);
    float* csh  = (float*)(smem_dyn + 131584);
    float* lbuf = fbuf;                         // epilogue reuse

    const int tid = threadIdx.x;
    const long rowBase = (long)blockIdx.x * BM2;
    const uint32_t fsh = (uint32_t)__cvta_generic_to_shared(fbuf);

    auto prefetch = [&](int kci, int st) {
        const uint32_t sbase = fsh + st * 32768u;
#pragma unroll
        for (int m = 0; m < 4; m++) {
            const int q  = tid + 512 * m;       // quad id 0..2047
            const int r  = q >> 3;
            const int kq = q & 7;
            const float* src = F + (rowBase + r) * D_ + kci * 32 + kq * 4;
            const uint32_t dst = sbase + (uint32_t)((r * 32 + ((kq ^ ((r >> 3) & 7)) << 2)) * 4);
            asm volatile("cp.async.ca.shared.global [%0], [%1], 16;" :: "r"(dst), "l"(src));
        }
    };

    prefetch(0, 0);
    asm volatile("cp.async.commit_group;");

    // one-time W transpose load (overlaps the first F prefetch)
    for (int idx = tid; idx < 512 * 32; idx += 512) {
        const int k = idx >> 5, c = idx & 31;
        wT[c * WT_STRIDE + k] = (c < V_) ? W[(long)k * V_ + c] : 0.f;
    }

    const int rg = tid >> 4;       // 0..31 : rows rg*8 + i
    const int cg = tid & 15;       // 0..15 : cols cg, cg+16
    const int fkey = (rg & 7) << 2;

    float bv[2];
#pragma unroll
    for (int j = 0; j < 2; j++) { int c = cg + 16 * j; bv[j] = (c < V_) ? bias[c] : 0.f; }

    u64 acc[8][2];
#pragma unroll
    for (int i = 0; i < 8; i++)
#pragma unroll
        for (int j = 0; j < 2; j++) acc[i][j] = 0ull;

    for (int kci = 0; kci < 16; kci++) {
        if (kci < 15) prefetch(kci + 1, (kci + 1) & 1);
        asm volatile("cp.async.commit_group;");
        asm volatile("cp.async.wait_group 1;");
        __syncthreads();

        const float* fstage = fbuf + (kci & 1) * 8192;
        const float* wbase  = wT + kci * 32;
#pragma unroll
        for (int kq = 0; kq < 8; kq++) {
            ulonglong2 f[8], w2[2];
#pragma unroll
            for (int i = 0; i < 8; i++)
                f[i] = *reinterpret_cast<const ulonglong2*>(
                    fstage + (rg * 8 + i) * 32 + ((kq << 2) ^ fkey));
#pragma unroll
            for (int j = 0; j < 2; j++)
                w2[j] = *reinterpret_cast<const ulonglong2*>(
                    wbase + (cg + 16 * j) * WT_STRIDE + kq * 4);
#pragma unroll
            for (int i = 0; i < 8; i++)
#pragma unroll
                for (int j = 0; j < 2; j++) FMA2(acc[i][j], f[i].x, w2[j].x);
#pragma unroll
            for (int i = 0; i < 8; i++)
#pragma unroll
                for (int j = 0; j < 2; j++) FMA2(acc[i][j], f[i].y, w2[j].y);
        }
        __syncthreads();
    }

    // ---- epilogue: combine k-pairs, bias, logits to smem [256][33] ----
#pragma unroll
    for (int i = 0; i < 8; i++)
#pragma unroll
        for (int j = 0; j < 2; j++) {
            const float lo = __uint_as_float((unsigned)(acc[i][j] & 0xffffffffull));
            const float hi = __uint_as_float((unsigned)(acc[i][j] >> 32));
            lbuf[(rg * 8 + i) * 33 + (cg + 16 * j)] = lo + hi + bv[j];
        }
    __syncthreads();

    // per-row (max*LOG2E + log2(sumexp)); threads 0..255 <-> rows
    if (tid < 256) {
        const float* r = &lbuf[tid * 33];
        float m = r[0];
#pragma unroll
        for (int v = 1; v < V_; v++) m = fmaxf(m, r[v]);
        float sum = 0.f;
#pragma unroll
        for (int v = 0; v < V_; v++) sum += ex2f((r[v] - m) * LOG2E);
        csh[tid] = m * LOG2E + lg2f(sum);
    }
    __syncthreads();

    // coalesced write of LOG2-probs
    float* outp = d_lp + rowBase * V_;
    for (int i = tid; i < BM2 * V_; i += 512) {
        const int row = i / V_;
        const int v   = i - row * V_;
        outp[i] = lbuf[row * 33 + v] * LOG2E - csh[row];
    }
}

// =====================================================================
// Kernel 2: CTC alpha recursion, LOG2 domain, PAIRED STATES.
// One block per batch, 224 threads (7 warps); thread i owns the pair
// (blank state 2i, label state 2i+1). Blank update = lse2 (2 MUFU),
// label = lse3 (3 MUFU) -> 5 MUFU/thread/step. Neighbor data is ONE
// float2 LDS. One __syncthreads per step; 4-deep lp prefetch (LDG).
// =====================================================================
__global__ __launch_bounds__(224) void ctc_kernel(
    const int* __restrict__ labels, const int* __restrict__ flens,
    const int* __restrict__ llens)
{
    __shared__ float2 pbuf[2][226];     // pbuf[.][i+1] = {alpha[2i], alpha[2i+1]}
    __shared__ int    lab_sh[L_];

    const int b    = blockIdx.x;
    const int tid  = threadIdx.x;
    const int flen = flens[b];
    const int llen = llens[b];

    for (int i = tid; i < L_; i += 224) lab_sh[i] = labels[b * L_ + i];
    if (tid == 0) {
        pbuf[0][0] = make_float2(NEGV, NEGV);
        pbuf[1][0] = make_float2(NEGV, NEGV);
    }
    __syncthreads();

    const int i = tid;                  // pair index; i >= 200 = dummy label
    int   ext   = CBLANK;
    bool  skip1 = false;
    if (i < 200) {
        ext   = lab_sh[i];
        skip1 = (i >= 1) && (ext != lab_sh[i - 1]);
    }

    const float* lpb = d_lp + (long)b * T_ * V_;

    // t = 0 init
    float a0 = NEGV, a1 = NEGV;
    if (i == 0) { a0 = lpb[CBLANK]; a1 = lpb[ext]; }
    pbuf[0][i + 1] = make_float2(a0, a1);

    // 4-deep prefetch: pB_k/pE_k hold rows t+k at loop entry (t=1)
    float pB0 = lpb[1 * V_ + CBLANK], pE0 = lpb[1 * V_ + ext];
    float pB1 = lpb[2 * V_ + CBLANK], pE1 = lpb[2 * V_ + ext];
    float pB2 = lpb[3 * V_ + CBLANK], pE2 = lpb[3 * V_ + ext];
    float pB3 = lpb[4 * V_ + CBLANK], pE3 = lpb[4 * V_ + ext];
    __syncthreads();

    int cur = 0;
    int t = 1;

#define CTC_STEP(PB, PE) do {                                                    \
    const float2 nb = pbuf[cur][i];     /* {alpha[2i-2], alpha[2i-1]} */         \
    const float n1 = nb.y;                                                       \
    const float new0 = lse2(a0, n1) + PB;                                        \
    const float new1 = lse3(a1, a0, skip1 ? n1 : NEGV) + PE;                     \
    a0 = new0; a1 = new1;                                                        \
    pbuf[cur ^ 1][i + 1] = make_float2(a0, a1);                                  \
    cur ^= 1;                                                                    \
    const int tn = min(t + 4, T_ - 1) * V_;                                      \
    PB = lpb[tn + CBLANK]; PE = lpb[tn + ext];                                   \
    __syncthreads();                                                             \
    t++;                                                                         \
} while (0)

    while (t + 3 < flen) {
        CTC_STEP(pB0, pE0); CTC_STEP(pB1, pE1);
        CTC_STEP(pB2, pE2); CTC_STEP(pB3, pE3);
    }
    while (t < flen) {
        CTC_STEP(pB0, pE0);
        pB0 = pB1; pE0 = pE1; pB1 = pB2; pE1 = pE2; pB2 = pB3; pE2 = pE3;
    }
#undef CTC_STEP

    if (tid == 0) {
        const float l1 = pbuf[cur][llen + 1].x;   // alpha[2*llen]
        const float l2 = pbuf[cur][llen].y;       // alpha[2*llen-1] (llen >= 50)
        const float ls = lse2(l1, l2);
        const float nll = -ls * LN2;
        d_loss[b] = (nll < 5e8f) ? nll / (float)llen : 0.f;
    }
}

// =====================================================================
// Kernel 3: deterministic fixed-order mean of 64 losses
// =====================================================================
__global__ void reduce_kernel(float* __restrict__ out)
{
    const int lane = threadIdx.x;
    float v = d_loss[lane] + d_loss[lane + 32];
#pragma unroll
    for (int o = 16; o > 0; o >>= 1) v += __shfl_down_sync(0xffffffffu, v, o);
    if (lane == 0) out[0] = v * (1.f / (float)B_);
}

// =====================================================================
extern "C" void kernel_launch(void* const* d_in, const int* in_sizes, int n_in,
                              void* d_out, int out_size)
{
    (void)in_sizes; (void)n_in; (void)out_size;
    const float* F      = (const float*)d_in[0];
    const float* W      = (const float*)d_in[1];
    const float* bias   = (const float*)d_in[2];
    const int*   labels = (const int*)d_in[3];
    const int*   flens  = (const int*)d_in[4];
    const int*   llens  = (const int*)d_in[5];
    float* out = (float*)d_out;

    cudaFuncSetAttribute(gemm_lsm_kernel,
                         cudaFuncAttributeMaxDynamicSharedMemorySize, SMEM_GEMM_BYTES);

    gemm_lsm_kernel<<<(B_ * T_) / BM2, 512, SMEM_GEMM_BYTES>>>(F, W, bias);
    ctc_kernel<<<B_, 224>>>(labels, flens, llens);
    reduce_kernel<<<1, 32>>>(out);
}